// round 10
// baseline (speedup 1.0000x reference)
#include <cuda_runtime.h>

// SoftBCELoss: fused 7-tap circular conv on binary target + BCE + full reduction,
// single kernel launch (threadfence last-block reduction).
// input:  (256, 2, 60000) fp32 in [0.01, 0.99]
// target: (256, 2, 60000) fp32 in {0, 1}
// out: [total, total_beat, total_down] fp32
//
// target_process == circular conv with weights
//   [1/8, 5/16, 21/32, 85/64, 21/32, 5/16, 1/8]   (offsets -3..+3)
// then min(.,1). Bit-exact in fp32 on binary inputs (dyadics, denom 64).
// alpha=gamma=0.5 => channel loss = 0.5 * sum(bce) / (256*60000).
// BCE accumulated in log2 domain; single ln2 scale at the end.

#define T_LEN   60000
#define TILE    4096
#define CHUNKS  15           // ceil(60000/4096); last chunk len = 2656
#define ROWS    512          // B*C
#define NBLK    (ROWS * CHUNKS)
#define THREADS 256
#define FULL_ITERS (TILE / 4 / THREADS)   // 4

__device__ float g_part[NBLK];
__device__ unsigned int g_count = 0;      // reset by last block each launch/replay

__device__ __forceinline__ float bce_group(float4 P, const float* q, float acc) {
    const float* pp = (const float*)&P;
    #pragma unroll
    for (int j = 0; j < 4; j++) {
        float ta = 1.328125f * q[j + 4];
        ta = fmaf(0.65625f, q[j + 3] + q[j + 5], ta);
        ta = fmaf(0.3125f,  q[j + 2] + q[j + 6], ta);
        ta = fmaf(0.125f,   q[j + 1] + q[j + 7], ta);
        ta = fminf(ta, 1.0f);

        float p   = pp[j];
        float lp  = __log2f(p);          // -100 clips never bind: p in [0.01,0.99]
        float l1p = __log2f(1.0f - p);
        // bce/ln2 = -(ta*lp + (1-ta)*l1p) = -l1p + ta*(l1p - lp)
        acc = fmaf(ta, l1p - lp, acc - l1p);
    }
    return acc;
}

__global__ void __launch_bounds__(THREADS)
bce_kernel(const float* __restrict__ inp, const float* __restrict__ tgt,
           float* __restrict__ out) {
    const int row   = blockIdx.x / CHUNKS;
    const int chunk = blockIdx.x % CHUNKS;
    const int start = chunk * TILE;
    const int len   = min(TILE, T_LEN - start);

    const float* __restrict__ trow = tgt + (size_t)row * T_LEN;
    const float* __restrict__ prow = inp + (size_t)row * T_LEN;

    __shared__ __align__(16) float s[TILE + 8];   // s[i] = target[start - 4 + i]

    // Interior staging: lane-contiguous float4 -> fully coalesced LDG.128.
    const float4* __restrict__ tv = (const float4*)(trow + start);
    float4* sv = (float4*)(s + 4);                // s 16B-aligned, +16B
    const int ngrp = len >> 2;
    #pragma unroll
    for (int it = 0; it < FULL_ITERS; it++) {
        int v = threadIdx.x + it * THREADS;
        if (v < ngrp) sv[v] = tv[v];
    }

    // Halo: 4 left + 4 right, circular wrap.
    if (threadIdx.x < 8) {
        int i = (threadIdx.x < 4) ? (int)threadIdx.x : (len + (int)threadIdx.x);
        int g = start - 4 + i;
        if (g < 0)      g += T_LEN;
        if (g >= T_LEN) g -= T_LEN;
        s[i] = trow[g];
    }
    __syncthreads();

    const float4* __restrict__ pv = (const float4*)(prow + start);
    float acc = 0.0f;                  // sum of bce in log2 units

    if (ngrp == TILE / 4) {
        // Full tile: compile-time trip count -> batched LDG.128 (MLP=4).
        float4 P[FULL_ITERS];
        #pragma unroll
        for (int it = 0; it < FULL_ITERS; it++)
            P[it] = pv[threadIdx.x + it * THREADS];

        #pragma unroll
        for (int it = 0; it < FULL_ITERS; it++) {
            int g = threadIdx.x + it * THREADS;
            float q[12];                       // s[4g .. 4g+11], 3 aligned LDS.128
            #pragma unroll
            for (int k = 0; k < 3; k++) {
                float4 f = ((const float4*)(s + 4 * g))[k];
                q[4*k + 0] = f.x; q[4*k + 1] = f.y;
                q[4*k + 2] = f.z; q[4*k + 3] = f.w;
            }
            acc = bce_group(P[it], q, acc);
        }
    } else {
        for (int g = threadIdx.x; g < ngrp; g += THREADS) {
            float4 P = pv[g];
            float q[12];
            #pragma unroll
            for (int k = 0; k < 3; k++) {
                float4 f = ((const float4*)(s + 4 * g))[k];
                q[4*k + 0] = f.x; q[4*k + 1] = f.y;
                q[4*k + 2] = f.z; q[4*k + 3] = f.w;
            }
            acc = bce_group(P, q, acc);
        }
    }

    #pragma unroll
    for (int off = 16; off > 0; off >>= 1)
        acc += __shfl_down_sync(0xffffffffu, acc, off);

    __shared__ float wsum[THREADS / 32];
    __shared__ bool is_last;
    if ((threadIdx.x & 31) == 0) wsum[threadIdx.x >> 5] = acc;
    __syncthreads();

    if (threadIdx.x == 0) {
        float b = 0.0f;
        #pragma unroll
        for (int w = 0; w < THREADS / 32; w++) b += wsum[w];
        g_part[blockIdx.x] = b;
        __threadfence();                               // release: publish partial
        unsigned int t = atomicAdd(&g_count, 1u);
        is_last = (t == NBLK - 1);
    }
    __syncthreads();

    if (is_last) {
        // Deterministic: full set of partials is fixed; this block sums in fixed
        // order. __ldcg (L2-only) avoids any possibility of stale L1 hits.
        __threadfence();                               // acquire
        double a0 = 0.0, a1 = 0.0;
        for (int i = threadIdx.x; i < NBLK; i += THREADS) {
            double v = (double)__ldcg(&g_part[i]);
            if (((i / CHUNKS) & 1) == 0) a0 += v; else a1 += v;
        }
        __shared__ double s0[THREADS], s1[THREADS];
        s0[threadIdx.x] = a0;
        s1[threadIdx.x] = a1;
        __syncthreads();
        for (int off = THREADS / 2; off > 0; off >>= 1) {
            if (threadIdx.x < off) {
                s0[threadIdx.x] += s0[threadIdx.x + off];
                s1[threadIdx.x] += s1[threadIdx.x + off];
            }
            __syncthreads();
        }
        if (threadIdx.x == 0) {
            const double scale = 0.6931471805599453 * 0.5 / (256.0 * 60000.0); // ln2*alpha/num
            double tb = s0[0] * scale;
            double td = s1[0] * scale;
            out[0] = (float)(tb + td);
            out[1] = (float)tb;
            out[2] = (float)td;
            g_count = 0;                               // re-arm for next replay
        }
    }
}

extern "C" void kernel_launch(void* const* d_in, const int* in_sizes, int n_in,
                              void* d_out, int out_size) {
    const float* inp = (const float*)d_in[0];
    const float* tgt = (const float*)d_in[1];
    float* out = (float*)d_out;

    bce_kernel<<<NBLK, THREADS>>>(inp, tgt, out);
}